// round 1
// baseline (speedup 1.0000x reference)
#include <cuda_runtime.h>
#include <math.h>

#define NV 778
#define VP 780            // padded with 2 sentinel verts
#define NJ 16
#define NCOMP 24
#define NBETA 10
#define FC 1554
#define NA 32
#define NB 8
#define NOBJ 16384

#define OFF_CMAP 0
#define OFF_PEN  (NB*NOBJ)                 // 131072
#define OFF_VERTS (OFF_PEN + 1)            // 131073
#define OFF_CC   (OFF_VERTS + NB*NV*3)     // 149745
// total out = 150513 floats

__device__ float4 g_verts4[NB * VP];       // x,y,z, 0.5*|v|^2
__device__ float  g_normals[NB * NV * 3];  // accumulated face normals

__constant__ int c_parents[NJ] = {-1,0,1,2,0,4,5,0,7,8,0,10,11,0,13,14};

// ---------------------------------------------------------------------------
// Kernel A: full MANO forward per batch (1 block per batch)
// ---------------------------------------------------------------------------
__global__ void __launch_bounds__(256) mano_kernel(
    const float* __restrict__ hand_pose, const float* __restrict__ hand_beta,
    const float* __restrict__ v_template, const float* __restrict__ shapedirs,
    const float* __restrict__ posedirs, const float* __restrict__ J_reg,
    const float* __restrict__ lbs_w, const float* __restrict__ pca,
    float* __restrict__ out)
{
    __shared__ float s_pose[32];
    __shared__ float s_beta[NBETA];
    __shared__ float s_full[NJ * 3];
    __shared__ float s_R[NJ * 9];
    __shared__ float s_J[NJ * 3];
    __shared__ float s_pf[(NJ - 1) * 9];
    __shared__ float s_vsh[NV * 3];
    __shared__ float s_vp[NV * 3];
    __shared__ float s_A[NJ * 12];

    const int b = blockIdx.x;
    const int tid = threadIdx.x;

    if (tid < 30) s_pose[tid] = hand_pose[b * 30 + tid];
    if (tid >= 32 && tid < 32 + NBETA) s_beta[tid - 32] = hand_beta[b * NBETA + (tid - 32)];
    // zero this batch's normal accumulator (before normals_kernel runs)
    for (int i = tid; i < NV * 3; i += 256) g_normals[b * NV * 3 + i] = 0.f;
    if (b == 0 && tid == 0) out[OFF_PEN] = 0.f;
    __syncthreads();

    // full pose: root (3) + hand_pose[6:] @ pca_comps (45)
    if (tid < 3) s_full[tid] = s_pose[3 + tid];
    if (tid >= 64 && tid < 64 + 45) {
        int p = tid - 64;
        float acc = 0.f;
        #pragma unroll
        for (int k = 0; k < NCOMP; k++) acc = fmaf(s_pose[6 + k], pca[k * 45 + p], acc);
        s_full[3 + p] = acc;
    }
    __syncthreads();

    // Rodrigues per joint
    if (tid < NJ) {
        float rx = s_full[tid * 3 + 0], ry = s_full[tid * 3 + 1], rz = s_full[tid * 3 + 2];
        float th = sqrtf(rx * rx + ry * ry + rz * rz + 1e-16f);
        float inv = 1.f / th;
        float kx = rx * inv, ky = ry * inv, kz = rz * inv;
        float c, s;
        sincosf(th, &s, &c);
        float ic = 1.f - c;
        float* R = &s_R[tid * 9];
        R[0] = c + ic * kx * kx;      R[1] = -s * kz + ic * kx * ky; R[2] =  s * ky + ic * kx * kz;
        R[3] =  s * kz + ic * ky * kx; R[4] = c + ic * ky * ky;      R[5] = -s * kx + ic * ky * kz;
        R[6] = -s * ky + ic * kz * kx; R[7] =  s * kx + ic * kz * ky; R[8] = c + ic * kz * kz;
    }

    // v_shaped = v_template + shapedirs @ beta
    for (int i = tid; i < NV * 3; i += 256) {
        const float* sd = shapedirs + i * NBETA;
        float acc = v_template[i];
        #pragma unroll
        for (int k = 0; k < NBETA; k++) acc = fmaf(sd[k], s_beta[k], acc);
        s_vsh[i] = acc;
    }
    __syncthreads();

    // J = J_regressor @ v_shaped
    if (tid < NJ * 3) {
        int j = tid / 3, d = tid % 3;
        const float* jr = J_reg + j * NV;
        float a0 = 0.f, a1 = 0.f, a2 = 0.f, a3 = 0.f;
        int v = 0;
        for (; v + 3 < NV; v += 4) {
            a0 = fmaf(jr[v + 0], s_vsh[(v + 0) * 3 + d], a0);
            a1 = fmaf(jr[v + 1], s_vsh[(v + 1) * 3 + d], a1);
            a2 = fmaf(jr[v + 2], s_vsh[(v + 2) * 3 + d], a2);
            a3 = fmaf(jr[v + 3], s_vsh[(v + 3) * 3 + d], a3);
        }
        for (; v < NV; v++) a0 = fmaf(jr[v], s_vsh[v * 3 + d], a0);
        s_J[tid] = (a0 + a1) + (a2 + a3);
    }
    // pose_feat = (R[1:] - I).flatten
    if (tid >= 64 && tid < 64 + (NJ - 1) * 9) {
        int p = tid - 64;
        int e = p % 9;
        float diag = ((e == 0) | (e == 4) | (e == 8)) ? 1.f : 0.f;
        s_pf[p] = s_R[(p / 9 + 1) * 9 + e] - diag;
    }
    __syncthreads();

    // v_posed = v_shaped + posedirs @ pose_feat
    for (int i = tid; i < NV * 3; i += 256) {
        const float* pd = posedirs + i * 135;
        float a0 = s_vsh[i], a1 = 0.f, a2 = 0.f, a3 = 0.f;
        int p = 0;
        for (; p + 3 < 135; p += 4) {
            a0 = fmaf(pd[p + 0], s_pf[p + 0], a0);
            a1 = fmaf(pd[p + 1], s_pf[p + 1], a1);
            a2 = fmaf(pd[p + 2], s_pf[p + 2], a2);
            a3 = fmaf(pd[p + 3], s_pf[p + 3], a3);
        }
        for (; p < 135; p++) a0 = fmaf(pd[p], s_pf[p], a0);
        s_vp[i] = (a0 + a1) + (a2 + a3);
    }

    // kinematic chain + corrective transforms (single thread, tiny)
    if (tid == 0) {
        float T[NJ][12];
        #pragma unroll
        for (int e = 0; e < 9; e++) T[0][(e / 3) * 4 + (e % 3)] = s_R[e];
        T[0][3] = s_J[0]; T[0][7] = s_J[1]; T[0][11] = s_J[2];
        for (int j = 1; j < NJ; j++) {
            int p = c_parents[j];
            float L[12];
            #pragma unroll
            for (int e = 0; e < 9; e++) L[(e / 3) * 4 + (e % 3)] = s_R[j * 9 + e];
            L[3]  = s_J[j * 3 + 0] - s_J[p * 3 + 0];
            L[7]  = s_J[j * 3 + 1] - s_J[p * 3 + 1];
            L[11] = s_J[j * 3 + 2] - s_J[p * 3 + 2];
            #pragma unroll
            for (int r = 0; r < 3; r++) {
                #pragma unroll
                for (int c2 = 0; c2 < 4; c2++) {
                    float acc = (c2 == 3) ? T[p][r * 4 + 3] : 0.f;
                    #pragma unroll
                    for (int k = 0; k < 3; k++) acc = fmaf(T[p][r * 4 + k], L[k * 4 + c2], acc);
                    T[j][r * 4 + c2] = acc;
                }
            }
        }
        for (int j = 0; j < NJ; j++) {
            float jx = s_J[j * 3 + 0], jy = s_J[j * 3 + 1], jz = s_J[j * 3 + 2];
            #pragma unroll
            for (int r = 0; r < 3; r++) {
                float r0 = T[j][r * 4 + 0], r1 = T[j][r * 4 + 1], r2 = T[j][r * 4 + 2];
                s_A[j * 12 + r * 4 + 0] = r0;
                s_A[j * 12 + r * 4 + 1] = r1;
                s_A[j * 12 + r * 4 + 2] = r2;
                s_A[j * 12 + r * 4 + 3] = T[j][r * 4 + 3] - (r0 * jx + r1 * jy + r2 * jz);
            }
        }
    }
    __syncthreads();

    // LBS skinning
    const float tx = s_pose[0], ty = s_pose[1], tz = s_pose[2];
    for (int v = tid; v < NV; v += 256) {
        const float* w = lbs_w + v * NJ;
        float M[12];
        #pragma unroll
        for (int k = 0; k < 12; k++) M[k] = 0.f;
        #pragma unroll
        for (int j = 0; j < NJ; j++) {
            float wj = w[j];
            #pragma unroll
            for (int k = 0; k < 12; k++) M[k] = fmaf(wj, s_A[j * 12 + k], M[k]);
        }
        float x = s_vp[v * 3 + 0], y = s_vp[v * 3 + 1], z = s_vp[v * 3 + 2];
        float px = fmaf(M[0], x, fmaf(M[1],  y, fmaf(M[2],  z, M[3])))  + tx;
        float py = fmaf(M[4], x, fmaf(M[5],  y, fmaf(M[6],  z, M[7])))  + ty;
        float pz = fmaf(M[8], x, fmaf(M[9],  y, fmaf(M[10], z, M[11]))) + tz;
        out[OFF_VERTS + (b * NV + v) * 3 + 0] = px;
        out[OFF_VERTS + (b * NV + v) * 3 + 1] = py;
        out[OFF_VERTS + (b * NV + v) * 3 + 2] = pz;
        g_verts4[b * VP + v] = make_float4(px, py, pz, 0.5f * (px * px + py * py + pz * pz));
    }
    // sentinel pad verts: t = dot - h = -1e30 -> never selected
    if (tid < 2) g_verts4[b * VP + NV + tid] = make_float4(0.f, 0.f, 0.f, 1e30f);
}

// ---------------------------------------------------------------------------
// Kernel B: scatter face normals
// ---------------------------------------------------------------------------
__global__ void __launch_bounds__(256) normals_kernel(const int* __restrict__ faces)
{
    int i = blockIdx.x * 256 + threadIdx.x;
    if (i >= NB * FC) return;
    int b = i / FC, f = i % FC;
    int i0 = faces[f * 3 + 0], i1 = faces[f * 3 + 1], i2 = faces[f * 3 + 2];
    float4 p0 = g_verts4[b * VP + i0];
    float4 p1 = g_verts4[b * VP + i1];
    float4 p2 = g_verts4[b * VP + i2];
    float e1x = p1.x - p0.x, e1y = p1.y - p0.y, e1z = p1.z - p0.z;
    float e2x = p2.x - p0.x, e2y = p2.y - p0.y, e2z = p2.z - p0.z;
    float nx = e1y * e2z - e1z * e2y;
    float ny = e1z * e2x - e1x * e2z;
    float nz = e1x * e2y - e1y * e2x;
    float* gn = g_normals + b * NV * 3;
    atomicAdd(&gn[i0 * 3 + 0], nx); atomicAdd(&gn[i0 * 3 + 1], ny); atomicAdd(&gn[i0 * 3 + 2], nz);
    atomicAdd(&gn[i1 * 3 + 0], nx); atomicAdd(&gn[i1 * 3 + 1], ny); atomicAdd(&gn[i1 * 3 + 2], nz);
    atomicAdd(&gn[i2 * 3 + 0], nx); atomicAdd(&gn[i2 * 3 + 1], ny); atomicAdd(&gn[i2 * 3 + 2], nz);
}

// ---------------------------------------------------------------------------
// Kernel C: fused NN search + cmap + penetration
// argmin d2 == argmax t where t = o.v - 0.5|v|^2 ; d2 = |o|^2 - 2 t
// ---------------------------------------------------------------------------
#define CHUNK 195   // 4 * 195 = 780 = VP

__global__ void __launch_bounds__(256) nn_kernel(const float* __restrict__ obj,
                                                 float* __restrict__ out)
{
    __shared__ float4 s_v[VP];
    __shared__ float  s_n[NV * 3];
    __shared__ float  s_red[8];

    const int b = blockIdx.x >> 6;
    const int tile = blockIdx.x & 63;
    const int tid = threadIdx.x;

    for (int v = tid; v < VP; v += 256) {
        s_v[v] = g_verts4[b * VP + v];
        if (v < NV) {
            float nx = g_normals[(b * NV + v) * 3 + 0];
            float ny = g_normals[(b * NV + v) * 3 + 1];
            float nz = g_normals[(b * NV + v) * 3 + 2];
            float inv = 1.f / (sqrtf(nx * nx + ny * ny + nz * nz) + 1e-8f);
            s_n[v * 3 + 0] = nx * inv;
            s_n[v * 3 + 1] = ny * inv;
            s_n[v * 3 + 2] = nz * inv;
        }
    }
    __syncthreads();

    const int n = tile * 256 + tid;
    const float* op = obj + (b * NOBJ + n) * 3;
    const float ox = op[0], oy = op[1], oz = op[2];
    const float o2 = ox * ox + oy * oy + oz * oz;

    float b0 = -3.4e38f, b1 = -3.4e38f, b2 = -3.4e38f, b3 = -3.4e38f;
    int i0 = 0, i1 = CHUNK, i2 = 2 * CHUNK, i3 = 3 * CHUNK;

    #pragma unroll 3
    for (int k = 0; k < CHUNK; k++) {
        float4 q; float t;
        q = s_v[k];
        t = fmaf(q.x, ox, fmaf(q.y, oy, fmaf(q.z, oz, -q.w)));
        if (t > b0) { b0 = t; i0 = k; }
        q = s_v[CHUNK + k];
        t = fmaf(q.x, ox, fmaf(q.y, oy, fmaf(q.z, oz, -q.w)));
        if (t > b1) { b1 = t; i1 = CHUNK + k; }
        q = s_v[2 * CHUNK + k];
        t = fmaf(q.x, ox, fmaf(q.y, oy, fmaf(q.z, oz, -q.w)));
        if (t > b2) { b2 = t; i2 = 2 * CHUNK + k; }
        q = s_v[3 * CHUNK + k];
        t = fmaf(q.x, ox, fmaf(q.y, oy, fmaf(q.z, oz, -q.w)));
        if (t > b3) { b3 = t; i3 = 3 * CHUNK + k; }
    }
    // merge in ascending chunk order with strict > : preserves first-argmin ties
    float best = b0; int bi = i0;
    if (b1 > best) { best = b1; bi = i1; }
    if (b2 > best) { best = b2; bi = i2; }
    if (b3 > best) { best = b3; bi = i3; }

    float d2 = fmaf(-2.f, best, o2);
    float cm = 2.f / (1.f + expf(100.f * d2));
    out[OFF_CMAP + b * NOBJ + n] = cm;

    float4 q = s_v[bi];
    float nx = s_n[bi * 3 + 0], ny = s_n[bi * 3 + 1], nz = s_n[bi * 3 + 2];
    float dp = (q.x - ox) * nx + (q.y - oy) * ny + (q.z - oz) * nz;
    float pen = (dp > 0.f) ? d2 : 0.f;

    #pragma unroll
    for (int off = 16; off > 0; off >>= 1) pen += __shfl_down_sync(0xffffffffu, pen, off);
    if ((tid & 31) == 0) s_red[tid >> 5] = pen;
    __syncthreads();
    if (tid == 0) {
        float s = 0.f;
        #pragma unroll
        for (int w = 0; w < 8; w++) s += s_red[w];
        atomicAdd(&out[OFF_PEN], s * (1.f / NB));
    }
}

// ---------------------------------------------------------------------------
// Kernel D: contact candidates
// ---------------------------------------------------------------------------
__global__ void __launch_bounds__(256) contact_kernel(const float* __restrict__ aw,
                                                      const int* __restrict__ afi,
                                                      float* __restrict__ out)
{
    int t = blockIdx.x * 256 + threadIdx.x;
    if (t >= NB * NA * 3) return;
    int b = t / (NA * 3);
    int r = t % (NA * 3);
    int a = r / 3, d = r % 3;
    float acc = 0.f;
    #pragma unroll
    for (int k = 0; k < 3; k++) {
        int vi = afi[a * 3 + k];
        acc = fmaf(aw[a * 3 + k], out[OFF_VERTS + (b * NV + vi) * 3 + d], acc);
    }
    out[OFF_CC + t] = acc;
}

// ---------------------------------------------------------------------------
extern "C" void kernel_launch(void* const* d_in, const int* in_sizes, int n_in,
                              void* d_out, int out_size)
{
    const float* hand_pose  = (const float*)d_in[0];
    const float* obj_points = (const float*)d_in[1];
    const float* hand_beta  = (const float*)d_in[2];
    const float* v_template = (const float*)d_in[3];
    const float* shapedirs  = (const float*)d_in[4];
    const float* posedirs   = (const float*)d_in[5];
    const float* J_reg      = (const float*)d_in[6];
    const float* lbs_w      = (const float*)d_in[7];
    const float* pca        = (const float*)d_in[8];
    const float* aw         = (const float*)d_in[9];
    const int*   faces      = (const int*)d_in[10];
    const int*   afi        = (const int*)d_in[11];
    float* out = (float*)d_out;

    mano_kernel<<<NB, 256>>>(hand_pose, hand_beta, v_template, shapedirs,
                             posedirs, J_reg, lbs_w, pca, out);
    normals_kernel<<<(NB * FC + 255) / 256, 256>>>(faces);
    nn_kernel<<<NB * 64, 256>>>(obj_points, out);
    contact_kernel<<<3, 256>>>(aw, afi, out);
}

// round 2
// speedup vs baseline: 1.2230x; 1.2230x over previous
#include <cuda_runtime.h>
#include <math.h>

#define NV 778
#define VP 784            // padded to 8*98 with sentinel verts
#define NJ 16
#define NCOMP 24
#define NBETA 10
#define FC 1554
#define NA 32
#define NB 8
#define NOBJ 16384

#define NCH 8
#define CL 98             // NCH*CL == VP

#define OFF_CMAP 0
#define OFF_PEN  (NB*NOBJ)                 // 131072
#define OFF_VERTS (OFF_PEN + 1)            // 131073
#define OFF_CC   (OFF_VERTS + NB*NV*3)     // 149745

__device__ float4 g_verts4[NB * VP];       // x,y,z, 0.5*|v|^2
__device__ float  g_normals[NB * NV * 3];  // NORMALIZED vertex normals

__constant__ int c_parents[NJ] = {-1,0,1,2,0,4,5,0,7,8,0,10,11,0,13,14};

// ---------------------------------------------------------------------------
// Kernel A: full MANO forward + face normals + contact candidates, per batch
// ---------------------------------------------------------------------------
__global__ void __launch_bounds__(256) mano_kernel(
    const float* __restrict__ hand_pose, const float* __restrict__ hand_beta,
    const float* __restrict__ v_template, const float* __restrict__ shapedirs,
    const float* __restrict__ posedirs, const float* __restrict__ J_reg,
    const float* __restrict__ lbs_w, const float* __restrict__ pca,
    const float* __restrict__ aw, const int* __restrict__ afi,
    const int* __restrict__ faces,
    float* __restrict__ out)
{
    __shared__ float s_pose[32];
    __shared__ float s_beta[NBETA];
    __shared__ float s_full[NJ * 3];
    __shared__ float s_R[NJ * 9];
    __shared__ float s_J[NJ * 3];
    __shared__ float s_T[NJ * 12];
    __shared__ float s_A[NJ * 12];
    __shared__ float s_vsh[NV * 3];
    __shared__ float s_vp[NV * 3];
    __shared__ float s_vout[NV * 3];
    __shared__ float s_nrm[NV * 3];

    const int b = blockIdx.x;
    const int tid = threadIdx.x;
    const int wid = tid >> 5;
    const int lane = tid & 31;

    // ---- phase 0: stage tiny inputs, zero accumulators
    if (tid < 30) s_pose[tid] = hand_pose[b * 30 + tid];
    if (tid >= 32 && tid < 32 + NBETA) s_beta[tid - 32] = hand_beta[b * NBETA + (tid - 32)];
    for (int i = tid; i < NV * 3; i += 256) s_nrm[i] = 0.f;
    if (b == 0 && tid == 0) out[OFF_PEN] = 0.f;
    __syncthreads();

    // ---- phase 1: full pose (root + pca), v_shaped (vector loads)
    if (tid < 3) s_full[tid] = s_pose[3 + tid];
    if (tid >= 64 && tid < 64 + 45) {
        int p = tid - 64;
        float acc = 0.f;
        #pragma unroll
        for (int k = 0; k < NCOMP; k++) acc = fmaf(s_pose[6 + k], pca[k * 45 + p], acc);
        s_full[3 + p] = acc;
    }
    for (int i = tid; i < NV * 3; i += 256) {
        const float2* sd = (const float2*)shapedirs + i * 5;
        float2 d0 = sd[0], d1 = sd[1], d2 = sd[2], d3 = sd[3], d4 = sd[4];
        float acc = v_template[i];
        acc = fmaf(d0.x, s_beta[0], acc); acc = fmaf(d0.y, s_beta[1], acc);
        acc = fmaf(d1.x, s_beta[2], acc); acc = fmaf(d1.y, s_beta[3], acc);
        acc = fmaf(d2.x, s_beta[4], acc); acc = fmaf(d2.y, s_beta[5], acc);
        acc = fmaf(d3.x, s_beta[6], acc); acc = fmaf(d3.y, s_beta[7], acc);
        acc = fmaf(d4.x, s_beta[8], acc); acc = fmaf(d4.y, s_beta[9], acc);
        s_vsh[i] = acc;
    }
    __syncthreads();

    // ---- phase 2: rodrigues (tid<16), then warp-cooperative J = J_reg @ v_shaped
    if (tid < NJ) {
        float rx = s_full[tid * 3 + 0], ry = s_full[tid * 3 + 1], rz = s_full[tid * 3 + 2];
        float th = sqrtf(rx * rx + ry * ry + rz * rz + 1e-16f);
        float inv = 1.f / th;
        float kx = rx * inv, ky = ry * inv, kz = rz * inv;
        float c, s;
        sincosf(th, &s, &c);
        float ic = 1.f - c;
        float* R = &s_R[tid * 9];
        R[0] = c + ic * kx * kx;       R[1] = -s * kz + ic * kx * ky; R[2] =  s * ky + ic * kx * kz;
        R[3] =  s * kz + ic * ky * kx; R[4] = c + ic * ky * ky;       R[5] = -s * kx + ic * ky * kz;
        R[6] = -s * ky + ic * kz * kx; R[7] =  s * kx + ic * kz * ky; R[8] = c + ic * kz * kz;
    }
    // 48 outputs; warp w handles o = w + 8q (q<6); lanes read coalesced J_reg
    #pragma unroll
    for (int q = 0; q < 6; q++) {
        int o = wid + 8 * q;
        int j = o / 3, d = o % 3;
        const float* jr = J_reg + j * NV;
        float acc = 0.f;
        #pragma unroll
        for (int k = 0; k < 25; k++) {
            int v = lane + 32 * k;
            if (v < NV) acc = fmaf(jr[v], s_vsh[v * 3 + d], acc);
        }
        #pragma unroll
        for (int off = 16; off > 0; off >>= 1) acc += __shfl_xor_sync(0xffffffffu, acc, off);
        if (lane == 0) s_J[o] = acc;
    }
    __syncthreads();

    // ---- phase 3: kinematic chain (warp 0, lanes<16, level-parallel) + v_posed
    if (wid == 0 && lane < 16) {
        const int j = lane;
        const int p = c_parents[j];
        float L[12];
        #pragma unroll
        for (int e = 0; e < 9; e++) L[(e / 3) * 4 + (e % 3)] = s_R[j * 9 + e];
        float jx = s_J[j * 3 + 0], jy = s_J[j * 3 + 1], jz = s_J[j * 3 + 2];
        if (j == 0) { L[3] = jx; L[7] = jy; L[11] = jz; }
        else {
            L[3]  = jx - s_J[p * 3 + 0];
            L[7]  = jy - s_J[p * 3 + 1];
            L[11] = jz - s_J[p * 3 + 2];
        }
        const int depth = (j == 0) ? 0 : ((j - 1) % 3) + 1;
        if (depth == 0) {
            #pragma unroll
            for (int k = 0; k < 12; k++) s_T[k] = L[k];
        }
        __syncwarp(0xffffu);
        #pragma unroll
        for (int l = 1; l <= 3; l++) {
            if (depth == l) {
                float Tp[12];
                #pragma unroll
                for (int k = 0; k < 12; k++) Tp[k] = s_T[p * 12 + k];
                #pragma unroll
                for (int r = 0; r < 3; r++) {
                    #pragma unroll
                    for (int c2 = 0; c2 < 4; c2++) {
                        float acc = (c2 == 3) ? Tp[r * 4 + 3] : 0.f;
                        #pragma unroll
                        for (int k = 0; k < 3; k++) acc = fmaf(Tp[r * 4 + k], L[k * 4 + c2], acc);
                        s_T[j * 12 + r * 4 + c2] = acc;
                    }
                }
            }
            __syncwarp(0xffffu);
        }
        // corrective: A = T with translation -= R*J
        #pragma unroll
        for (int r = 0; r < 3; r++) {
            float r0 = s_T[j * 12 + r * 4 + 0], r1 = s_T[j * 12 + r * 4 + 1], r2 = s_T[j * 12 + r * 4 + 2];
            s_A[j * 12 + r * 4 + 0] = r0;
            s_A[j * 12 + r * 4 + 1] = r1;
            s_A[j * 12 + r * 4 + 2] = r2;
            s_A[j * 12 + r * 4 + 3] = s_T[j * 12 + r * 4 + 3] - (r0 * jx + r1 * jy + r2 * jz);
        }
    }

    // v_posed: warp-cooperative rows, pose_feat kept in registers per lane
    {
        float pfr[5];
        #pragma unroll
        for (int jj = 0; jj < 5; jj++) {
            int p = lane + 32 * jj;
            if (p < 135) {
                int e = p % 9;
                float diag = ((e == 0) | (e == 4) | (e == 8)) ? 1.f : 0.f;
                pfr[jj] = s_R[9 + p] - diag;
            } else pfr[jj] = 0.f;
        }
        for (int i = wid; i < NV * 3; i += 8) {
            const float* pd = posedirs + i * 135;
            float a = pfr[0] * pd[lane];
            a = fmaf(pfr[1], pd[lane + 32], a);
            a = fmaf(pfr[2], pd[lane + 64], a);
            a = fmaf(pfr[3], pd[lane + 96], a);
            if (lane < 7) a = fmaf(pfr[4], pd[lane + 128], a);
            #pragma unroll
            for (int off = 16; off > 0; off >>= 1) a += __shfl_xor_sync(0xffffffffu, a, off);
            if (lane == 0) s_vp[i] = s_vsh[i] + a;
        }
    }
    __syncthreads();

    // ---- phase 4: LBS skinning (float4 weight loads)
    const float tx = s_pose[0], ty = s_pose[1], tz = s_pose[2];
    for (int v = tid; v < NV; v += 256) {
        const float4* w4 = (const float4*)(lbs_w + v * NJ);
        float4 a0 = w4[0], a1 = w4[1], a2 = w4[2], a3 = w4[3];
        float wj[16] = {a0.x,a0.y,a0.z,a0.w, a1.x,a1.y,a1.z,a1.w,
                        a2.x,a2.y,a2.z,a2.w, a3.x,a3.y,a3.z,a3.w};
        float M[12];
        #pragma unroll
        for (int k = 0; k < 12; k++) M[k] = 0.f;
        #pragma unroll
        for (int j = 0; j < NJ; j++) {
            #pragma unroll
            for (int k = 0; k < 12; k++) M[k] = fmaf(wj[j], s_A[j * 12 + k], M[k]);
        }
        float x = s_vp[v * 3 + 0], y = s_vp[v * 3 + 1], z = s_vp[v * 3 + 2];
        float px = fmaf(M[0], x, fmaf(M[1],  y, fmaf(M[2],  z, M[3])))  + tx;
        float py = fmaf(M[4], x, fmaf(M[5],  y, fmaf(M[6],  z, M[7])))  + ty;
        float pz = fmaf(M[8], x, fmaf(M[9],  y, fmaf(M[10], z, M[11]))) + tz;
        s_vout[v * 3 + 0] = px; s_vout[v * 3 + 1] = py; s_vout[v * 3 + 2] = pz;
        out[OFF_VERTS + (b * NV + v) * 3 + 0] = px;
        out[OFF_VERTS + (b * NV + v) * 3 + 1] = py;
        out[OFF_VERTS + (b * NV + v) * 3 + 2] = pz;
        g_verts4[b * VP + v] = make_float4(px, py, pz, 0.5f * (px * px + py * py + pz * pz));
    }
    if (tid < VP - NV)  // sentinels: t = dot - 1e30 -> never selected
        g_verts4[b * VP + NV + tid] = make_float4(0.f, 0.f, 0.f, 1e30f);
    __syncthreads();

    // ---- phase 5: face normals into smem atomics; contact candidates
    for (int f = tid; f < FC; f += 256) {
        int i0 = faces[f * 3 + 0], i1 = faces[f * 3 + 1], i2 = faces[f * 3 + 2];
        float p0x = s_vout[i0*3+0], p0y = s_vout[i0*3+1], p0z = s_vout[i0*3+2];
        float e1x = s_vout[i1*3+0]-p0x, e1y = s_vout[i1*3+1]-p0y, e1z = s_vout[i1*3+2]-p0z;
        float e2x = s_vout[i2*3+0]-p0x, e2y = s_vout[i2*3+1]-p0y, e2z = s_vout[i2*3+2]-p0z;
        float nx = e1y * e2z - e1z * e2y;
        float ny = e1z * e2x - e1x * e2z;
        float nz = e1x * e2y - e1y * e2x;
        atomicAdd(&s_nrm[i0*3+0], nx); atomicAdd(&s_nrm[i0*3+1], ny); atomicAdd(&s_nrm[i0*3+2], nz);
        atomicAdd(&s_nrm[i1*3+0], nx); atomicAdd(&s_nrm[i1*3+1], ny); atomicAdd(&s_nrm[i1*3+2], nz);
        atomicAdd(&s_nrm[i2*3+0], nx); atomicAdd(&s_nrm[i2*3+1], ny); atomicAdd(&s_nrm[i2*3+2], nz);
    }
    if (tid < NA * 3) {
        int a = tid / 3, d = tid % 3;
        float acc = 0.f;
        #pragma unroll
        for (int k = 0; k < 3; k++) {
            int vi = afi[a * 3 + k];
            acc = fmaf(aw[a * 3 + k], s_vout[vi * 3 + d], acc);
        }
        out[OFF_CC + b * NA * 3 + tid] = acc;
    }
    __syncthreads();

    // ---- phase 6: normalize vertex normals once, store
    for (int v = tid; v < NV; v += 256) {
        float nx = s_nrm[v*3+0], ny = s_nrm[v*3+1], nz = s_nrm[v*3+2];
        float inv = 1.f / (sqrtf(nx*nx + ny*ny + nz*nz) + 1e-8f);
        g_normals[(b * NV + v) * 3 + 0] = nx * inv;
        g_normals[(b * NV + v) * 3 + 1] = ny * inv;
        g_normals[(b * NV + v) * 3 + 2] = nz * inv;
    }
}

// ---------------------------------------------------------------------------
// Kernel B: fused NN search + cmap + penetration
// argmin d2 == argmax t, t = o.v - 0.5|v|^2 ; d2 = |o|^2 - 2t
// blocked max (8 chunks of 98) + deferred exact index recovery
// ---------------------------------------------------------------------------
__device__ __forceinline__ float nn_finish(const float4* s_v, int b, int p,
                                           float ox, float oy, float oz,
                                           const float* m, float* __restrict__ out)
{
    float best = m[0]; int bc = 0;
    #pragma unroll
    for (int c = 1; c < NCH; c++) if (m[c] > best) { best = m[c]; bc = c; }
    const int base = bc * CL;
    int idx = -1;
    for (int k = 0; k < CL; k++) {
        float4 q = s_v[base + k];
        float t = fmaf(q.x, ox, fmaf(q.y, oy, fmaf(q.z, oz, -q.w)));
        if (idx < 0 && t == best) idx = k;
    }
    const int bi = base + idx;
    float o2 = ox * ox + oy * oy + oz * oz;
    float d2 = fmaf(-2.f, best, o2);
    out[OFF_CMAP + b * NOBJ + p] = 2.f / (1.f + __expf(100.f * d2));
    float4 q = s_v[bi];
    const float* gn = g_normals + (b * NV + bi) * 3;
    float dp = (q.x - ox) * gn[0] + (q.y - oy) * gn[1] + (q.z - oz) * gn[2];
    return (dp > 0.f) ? d2 : 0.f;
}

__global__ void __launch_bounds__(256) nn_kernel(const float* __restrict__ obj,
                                                 float* __restrict__ out)
{
    __shared__ float4 s_v[VP];
    __shared__ float s_red[8];

    const int b = blockIdx.x >> 5;
    const int tile = blockIdx.x & 31;
    const int tid = threadIdx.x;

    for (int v = tid; v < VP; v += 256) s_v[v] = g_verts4[b * VP + v];
    __syncthreads();

    const int p0 = tile * 512 + tid;
    const int p1 = p0 + 256;
    const float* oA = obj + (b * NOBJ + p0) * 3;
    const float* oB = obj + (b * NOBJ + p1) * 3;
    const float ax = oA[0], ay = oA[1], az = oA[2];
    const float bx = oB[0], by = oB[1], bz = oB[2];

    float mA[NCH], mB[NCH];
    #pragma unroll
    for (int c = 0; c < NCH; c++) { mA[c] = -3.4e38f; mB[c] = -3.4e38f; }

    #pragma unroll 2
    for (int k = 0; k < CL; k++) {
        #pragma unroll
        for (int c = 0; c < NCH; c++) {
            float4 q = s_v[c * CL + k];
            float tA = fmaf(q.x, ax, fmaf(q.y, ay, fmaf(q.z, az, -q.w)));
            mA[c] = fmaxf(mA[c], tA);
            float tB = fmaf(q.x, bx, fmaf(q.y, by, fmaf(q.z, bz, -q.w)));
            mB[c] = fmaxf(mB[c], tB);
        }
    }

    float pen = nn_finish(s_v, b, p0, ax, ay, az, mA, out)
              + nn_finish(s_v, b, p1, bx, by, bz, mB, out);

    #pragma unroll
    for (int off = 16; off > 0; off >>= 1) pen += __shfl_down_sync(0xffffffffu, pen, off);
    if ((tid & 31) == 0) s_red[tid >> 5] = pen;
    __syncthreads();
    if (tid == 0) {
        float s = 0.f;
        #pragma unroll
        for (int w = 0; w < 8; w++) s += s_red[w];
        atomicAdd(&out[OFF_PEN], s * (1.f / NB));
    }
}

// ---------------------------------------------------------------------------
extern "C" void kernel_launch(void* const* d_in, const int* in_sizes, int n_in,
                              void* d_out, int out_size)
{
    const float* hand_pose  = (const float*)d_in[0];
    const float* obj_points = (const float*)d_in[1];
    const float* hand_beta  = (const float*)d_in[2];
    const float* v_template = (const float*)d_in[3];
    const float* shapedirs  = (const float*)d_in[4];
    const float* posedirs   = (const float*)d_in[5];
    const float* J_reg      = (const float*)d_in[6];
    const float* lbs_w      = (const float*)d_in[7];
    const float* pca        = (const float*)d_in[8];
    const float* aw         = (const float*)d_in[9];
    const int*   faces      = (const int*)d_in[10];
    const int*   afi        = (const int*)d_in[11];
    float* out = (float*)d_out;

    mano_kernel<<<NB, 256>>>(hand_pose, hand_beta, v_template, shapedirs,
                             posedirs, J_reg, lbs_w, pca, aw, afi, faces, out);
    nn_kernel<<<NB * 32, 256>>>(obj_points, out);
}

// round 7
// speedup vs baseline: 1.3357x; 1.0921x over previous
#include <cuda_runtime.h>
#include <math.h>

#define NV 778
#define VP 784            // 8*98, padded with sentinels
#define NJ 16
#define NCOMP 24
#define NBETA 10
#define FC 1554
#define NA 32
#define NB 8
#define NOBJ 16384

#define NCH 8
#define CL 98             // NCH*CL == VP

#define OFF_CMAP 0
#define OFF_PEN  (NB*NOBJ)
#define OFF_VERTS (OFF_PEN + 1)
#define OFF_CC   (OFF_VERTS + NB*NV*3)

__device__ float4 g_verts4[NB * VP];       // x,y,z, 0.5*|v|^2
__device__ float  g_normals[NB * NV * 3];  // normalized vertex normals
__device__ float  g_JS[48 * NBETA];        // (J_reg @ shapedirs)[j,d,k]
__device__ float  g_JT[48];                // (J_reg @ v_template)[j,d]
__device__ float  g_A[NB * NJ * 12];       // skinning transforms (corrected)
__device__ float  g_pf[NB * 135];          // pose features

__constant__ int c_parents[NJ] = {-1,0,1,2,0,4,5,0,7,8,0,10,11,0,13,14};

// ---------------------------------------------------------------------------
// prep_a: batch-independent factorization  JS = J_reg@shapedirs, JT = J_reg@vt
// grid 48 (one block per (j,d)), 128 threads
// ---------------------------------------------------------------------------
__global__ void __launch_bounds__(128) prep_a_kernel(
    const float* __restrict__ J_reg, const float* __restrict__ shapedirs,
    const float* __restrict__ v_template, float* __restrict__ out)
{
    const int o = blockIdx.x;           // 0..47
    const int j = o / 3, d = o % 3;
    const int tid = threadIdx.x;
    const int lane = tid & 31, wid = tid >> 5;
    __shared__ float s_red[4][11];

    float acc[11];
    #pragma unroll
    for (int k = 0; k < 11; k++) acc[k] = 0.f;

    for (int v = tid; v < NV; v += 128) {
        float w = J_reg[j * NV + v];
        const float2* sd = (const float2*)(shapedirs + (v * 3 + d) * NBETA);
        float2 s0 = sd[0], s1 = sd[1], s2 = sd[2], s3 = sd[3], s4 = sd[4];
        acc[0] = fmaf(w, s0.x, acc[0]); acc[1] = fmaf(w, s0.y, acc[1]);
        acc[2] = fmaf(w, s1.x, acc[2]); acc[3] = fmaf(w, s1.y, acc[3]);
        acc[4] = fmaf(w, s2.x, acc[4]); acc[5] = fmaf(w, s2.y, acc[5]);
        acc[6] = fmaf(w, s3.x, acc[6]); acc[7] = fmaf(w, s3.y, acc[7]);
        acc[8] = fmaf(w, s4.x, acc[8]); acc[9] = fmaf(w, s4.y, acc[9]);
        acc[10] = fmaf(w, v_template[v * 3 + d], acc[10]);
    }
    #pragma unroll
    for (int k = 0; k < 11; k++) {
        #pragma unroll
        for (int off = 16; off > 0; off >>= 1)
            acc[k] += __shfl_xor_sync(0xffffffffu, acc[k], off);
    }
    if (lane == 0) {
        #pragma unroll
        for (int k = 0; k < 11; k++) s_red[wid][k] = acc[k];
    }
    __syncthreads();
    if (tid < 11) {
        float s = s_red[0][tid] + s_red[1][tid] + s_red[2][tid] + s_red[3][tid];
        if (tid < 10) g_JS[o * NBETA + tid] = s;
        else          g_JT[o] = s;
    }
    if (blockIdx.x == 0 && tid == 0) out[OFF_PEN] = 0.f;
}

// ---------------------------------------------------------------------------
// prep_b: pose pipeline for all batches (1 block)
// ---------------------------------------------------------------------------
__global__ void __launch_bounds__(256) prep_b_kernel(
    const float* __restrict__ hand_pose, const float* __restrict__ hand_beta,
    const float* __restrict__ pca)
{
    __shared__ float s_pose[NB * 30];
    __shared__ float s_beta[NB * NBETA];
    __shared__ float s_full[NB * 48];
    __shared__ float s_R[NB * NJ * 9];
    __shared__ float s_J[NB * 48];
    __shared__ float s_T[NB * NJ * 12];

    const int tid = threadIdx.x;
    if (tid < 240) s_pose[tid] = hand_pose[tid];
    if (tid < 80)  s_beta[tid] = hand_beta[tid];
    __syncthreads();

    // full pose: root + pca expansion
    for (int t = tid; t < NB * 48; t += 256) {
        int b = t / 48, p = t % 48;
        float r;
        if (p < 3) r = s_pose[b * 30 + 3 + p];
        else {
            int q = p - 3;
            float acc = 0.f;
            #pragma unroll
            for (int k = 0; k < NCOMP; k++)
                acc = fmaf(s_pose[b * 30 + 6 + k], pca[k * 45 + q], acc);
            r = acc;
        }
        s_full[t] = r;
    }
    __syncthreads();

    // rodrigues for 128 (b,j)
    if (tid < NB * NJ) {
        int b = tid >> 4, j = tid & 15;
        const float* f = &s_full[b * 48 + j * 3];
        float rx = f[0], ry = f[1], rz = f[2];
        float th = sqrtf(rx * rx + ry * ry + rz * rz + 1e-16f);
        float inv = 1.f / th;
        float kx = rx * inv, ky = ry * inv, kz = rz * inv;
        float c, s;
        sincosf(th, &s, &c);
        float ic = 1.f - c;
        float* R = &s_R[tid * 9];
        R[0] = c + ic * kx * kx;       R[1] = -s * kz + ic * kx * ky; R[2] =  s * ky + ic * kx * kz;
        R[3] =  s * kz + ic * ky * kx; R[4] = c + ic * ky * ky;       R[5] = -s * kx + ic * ky * kz;
        R[6] = -s * ky + ic * kz * kx; R[7] =  s * kx + ic * kz * ky; R[8] = c + ic * kz * kz;
    }
    __syncthreads();

    // pose features
    for (int t = tid; t < NB * 135; t += 256) {
        int b = t / 135, p = t % 135;
        int e = p % 9;
        float diag = ((e == 0) | (e == 4) | (e == 8)) ? 1.f : 0.f;
        g_pf[t] = s_R[(b * NJ + 1 + p / 9) * 9 + e] - diag;
    }
    // joints: J = JT + JS @ beta
    for (int t = tid; t < NB * 48; t += 256) {
        int b = t / 48, o = t % 48;
        float acc = g_JT[o];
        #pragma unroll
        for (int k = 0; k < NBETA; k++)
            acc = fmaf(g_JS[o * NBETA + k], s_beta[b * NBETA + k], acc);
        s_J[t] = acc;
    }
    __syncthreads();

    // kinematic chain, level-parallel across all (b,j)
    float L[12];
    int b = tid >> 4, j = tid & 15, depth = 4, p = 0;
    if (tid < NB * NJ) {
        p = c_parents[j];
        #pragma unroll
        for (int e = 0; e < 9; e++) L[(e / 3) * 4 + (e % 3)] = s_R[(b * NJ + j) * 9 + e];
        float jx = s_J[b * 48 + j * 3 + 0];
        float jy = s_J[b * 48 + j * 3 + 1];
        float jz = s_J[b * 48 + j * 3 + 2];
        if (j == 0) { L[3] = jx; L[7] = jy; L[11] = jz; depth = 0; }
        else {
            L[3]  = jx - s_J[b * 48 + p * 3 + 0];
            L[7]  = jy - s_J[b * 48 + p * 3 + 1];
            L[11] = jz - s_J[b * 48 + p * 3 + 2];
            depth = ((j - 1) % 3) + 1;
        }
        if (depth == 0) {
            #pragma unroll
            for (int k = 0; k < 12; k++) s_T[b * NJ * 12 + k] = L[k];
        }
    }
    __syncthreads();
    #pragma unroll
    for (int l = 1; l <= 3; l++) {
        if (tid < NB * NJ && depth == l) {
            float Tp[12];
            #pragma unroll
            for (int k = 0; k < 12; k++) Tp[k] = s_T[(b * NJ + p) * 12 + k];
            #pragma unroll
            for (int r = 0; r < 3; r++) {
                #pragma unroll
                for (int c2 = 0; c2 < 4; c2++) {
                    float acc = (c2 == 3) ? Tp[r * 4 + 3] : 0.f;
                    #pragma unroll
                    for (int k = 0; k < 3; k++)
                        acc = fmaf(Tp[r * 4 + k], L[k * 4 + c2], acc);
                    s_T[(b * NJ + j) * 12 + r * 4 + c2] = acc;
                }
            }
        }
        __syncthreads();
    }
    if (tid < NB * NJ) {
        float jx = s_J[b * 48 + j * 3 + 0];
        float jy = s_J[b * 48 + j * 3 + 1];
        float jz = s_J[b * 48 + j * 3 + 2];
        const float* T = &s_T[(b * NJ + j) * 12];
        float* A = &g_A[(b * NJ + j) * 12];
        #pragma unroll
        for (int r = 0; r < 3; r++) {
            float r0 = T[r * 4 + 0], r1 = T[r * 4 + 1], r2 = T[r * 4 + 2];
            A[r * 4 + 0] = r0; A[r * 4 + 1] = r1; A[r * 4 + 2] = r2;
            A[r * 4 + 3] = T[r * 4 + 3] - (r0 * jx + r1 * jy + r2 * jz);
        }
    }
}

// ---------------------------------------------------------------------------
// vert: v_shaped + posedirs einsum + LBS. grid NB*8 (98 verts/block), 256 thr
// ---------------------------------------------------------------------------
__global__ void __launch_bounds__(256) vert_kernel(
    const float* __restrict__ v_template, const float* __restrict__ shapedirs,
    const float* __restrict__ posedirs, const float* __restrict__ lbs_w,
    const float* __restrict__ hand_pose, const float* __restrict__ hand_beta,
    float* __restrict__ out)
{
    __shared__ float s_A[NJ * 12];
    __shared__ float s_vp[CL * 3];
    __shared__ float s_beta[NBETA];

    const int b = blockIdx.x >> 3;
    const int chunk = blockIdx.x & 7;
    const int vbase = chunk * CL;
    const int tid = threadIdx.x;
    const int wid = tid >> 5, lane = tid & 31;

    if (tid < NJ * 12) s_A[tid] = g_A[b * NJ * 12 + tid];
    if (tid >= 192 && tid < 192 + NBETA) s_beta[tid - 192] = hand_beta[b * NBETA + (tid - 192)];
    __syncthreads();

    // pose features in registers (per lane)
    float pfr[5];
    #pragma unroll
    for (int jj = 0; jj < 5; jj++) {
        int p = lane + 32 * jj;
        pfr[jj] = (p < 135) ? g_pf[b * 135 + p] : 0.f;
    }

    // rows: 294 = 98 verts * 3 dims, warp-cooperative
    for (int r = wid; r < CL * 3; r += 8) {
        int v = vbase + r / 3;
        if (v < NV) {
            int d = r - (r / 3) * 3;
            int row = v * 3 + d;
            const float* pd = posedirs + row * 135;
            float a = pfr[0] * pd[lane];
            a = fmaf(pfr[1], pd[lane + 32], a);
            a = fmaf(pfr[2], pd[lane + 64], a);
            a = fmaf(pfr[3], pd[lane + 96], a);
            if (lane < 7) a = fmaf(pfr[4], pd[lane + 128], a);
            #pragma unroll
            for (int off = 16; off > 0; off >>= 1)
                a += __shfl_xor_sync(0xffffffffu, a, off);
            if (lane == 0) {
                // v_shaped base (scalar)
                const float* sd = shapedirs + row * NBETA;
                float base = v_template[row];
                #pragma unroll
                for (int k = 0; k < NBETA; k++) base = fmaf(sd[k], s_beta[k], base);
                s_vp[r] = base + a;
            }
        }
    }
    __syncthreads();

    // LBS for 98 verts
    if (tid < CL) {
        int v = vbase + tid;
        if (v < NV) {
            const float4* w4 = (const float4*)(lbs_w + v * NJ);
            float4 a0 = w4[0], a1 = w4[1], a2 = w4[2], a3 = w4[3];
            float wj[16] = {a0.x,a0.y,a0.z,a0.w, a1.x,a1.y,a1.z,a1.w,
                            a2.x,a2.y,a2.z,a2.w, a3.x,a3.y,a3.z,a3.w};
            float M[12];
            #pragma unroll
            for (int k = 0; k < 12; k++) M[k] = 0.f;
            #pragma unroll
            for (int j = 0; j < NJ; j++) {
                #pragma unroll
                for (int k = 0; k < 12; k++) M[k] = fmaf(wj[j], s_A[j * 12 + k], M[k]);
            }
            float x = s_vp[tid * 3 + 0], y = s_vp[tid * 3 + 1], z = s_vp[tid * 3 + 2];
            float px = fmaf(M[0], x, fmaf(M[1],  y, fmaf(M[2],  z, M[3])))  + hand_pose[b * 30 + 0];
            float py = fmaf(M[4], x, fmaf(M[5],  y, fmaf(M[6],  z, M[7])))  + hand_pose[b * 30 + 1];
            float pz = fmaf(M[8], x, fmaf(M[9],  y, fmaf(M[10], z, M[11]))) + hand_pose[b * 30 + 2];
            out[OFF_VERTS + (b * NV + v) * 3 + 0] = px;
            out[OFF_VERTS + (b * NV + v) * 3 + 1] = py;
            out[OFF_VERTS + (b * NV + v) * 3 + 2] = pz;
            g_verts4[b * VP + v] = make_float4(px, py, pz, 0.5f * (px * px + py * py + pz * pz));
        } else {
            g_verts4[b * VP + v] = make_float4(0.f, 0.f, 0.f, 1e30f);  // sentinel
        }
    }
}

// ---------------------------------------------------------------------------
// norm: face normals (smem atomics) + normalize + contact candidates. grid NB
// ---------------------------------------------------------------------------
__global__ void __launch_bounds__(256) norm_kernel(
    const int* __restrict__ faces, const float* __restrict__ aw,
    const int* __restrict__ afi, float* __restrict__ out)
{
    __shared__ float s_v3[NV * 3];
    __shared__ float s_nrm[NV * 3];

    const int b = blockIdx.x;
    const int tid = threadIdx.x;

    for (int v = tid; v < NV; v += 256) {
        float4 q = g_verts4[b * VP + v];
        s_v3[v * 3 + 0] = q.x; s_v3[v * 3 + 1] = q.y; s_v3[v * 3 + 2] = q.z;
    }
    for (int i = tid; i < NV * 3; i += 256) s_nrm[i] = 0.f;
    __syncthreads();

    for (int f = tid; f < FC; f += 256) {
        int i0 = faces[f * 3 + 0], i1 = faces[f * 3 + 1], i2 = faces[f * 3 + 2];
        float p0x = s_v3[i0*3+0], p0y = s_v3[i0*3+1], p0z = s_v3[i0*3+2];
        float e1x = s_v3[i1*3+0]-p0x, e1y = s_v3[i1*3+1]-p0y, e1z = s_v3[i1*3+2]-p0z;
        float e2x = s_v3[i2*3+0]-p0x, e2y = s_v3[i2*3+1]-p0y, e2z = s_v3[i2*3+2]-p0z;
        float nx = e1y * e2z - e1z * e2y;
        float ny = e1z * e2x - e1x * e2z;
        float nz = e1x * e2y - e1y * e2x;
        atomicAdd(&s_nrm[i0*3+0], nx); atomicAdd(&s_nrm[i0*3+1], ny); atomicAdd(&s_nrm[i0*3+2], nz);
        atomicAdd(&s_nrm[i1*3+0], nx); atomicAdd(&s_nrm[i1*3+1], ny); atomicAdd(&s_nrm[i1*3+2], nz);
        atomicAdd(&s_nrm[i2*3+0], nx); atomicAdd(&s_nrm[i2*3+1], ny); atomicAdd(&s_nrm[i2*3+2], nz);
    }
    if (tid < NA * 3) {
        int a = tid / 3, d = tid % 3;
        float acc = 0.f;
        #pragma unroll
        for (int k = 0; k < 3; k++)
            acc = fmaf(aw[a * 3 + k], s_v3[afi[a * 3 + k] * 3 + d], acc);
        out[OFF_CC + b * NA * 3 + tid] = acc;
    }
    __syncthreads();

    for (int v = tid; v < NV; v += 256) {
        float nx = s_nrm[v*3+0], ny = s_nrm[v*3+1], nz = s_nrm[v*3+2];
        float inv = 1.f / (sqrtf(nx*nx + ny*ny + nz*nz) + 1e-8f);
        g_normals[(b * NV + v) * 3 + 0] = nx * inv;
        g_normals[(b * NV + v) * 3 + 1] = ny * inv;
        g_normals[(b * NV + v) * 3 + 2] = nz * inv;
    }
}

// ---------------------------------------------------------------------------
// nn: fused NN + cmap + penetration. 512 blocks x 256 thr, 1 pt/thread
// argmin d2 == argmax t, t = o.v - 0.5|v|^2 ; d2 = |o|^2 - 2t
// ---------------------------------------------------------------------------
__global__ void __launch_bounds__(256) nn_kernel(const float* __restrict__ obj,
                                                 float* __restrict__ out)
{
    __shared__ float4 s_v[VP];
    __shared__ float s_red[8];

    const int b = blockIdx.x >> 6;
    const int tile = blockIdx.x & 63;
    const int tid = threadIdx.x;

    for (int v = tid; v < VP; v += 256) s_v[v] = g_verts4[b * VP + v];
    __syncthreads();

    const int pt = tile * 256 + tid;
    const float* op = obj + (b * NOBJ + pt) * 3;
    const float ox = op[0], oy = op[1], oz = op[2];

    float m[NCH];
    #pragma unroll
    for (int c = 0; c < NCH; c++) {
        const float4* sv = s_v + c * CL;
        float mm = -3.4e38f;
        #pragma unroll 7
        for (int k = 0; k < CL; k++) {
            float4 q = sv[k];
            mm = fmaxf(mm, fmaf(q.x, ox, fmaf(q.y, oy, fmaf(q.z, oz, -q.w))));
        }
        m[c] = mm;
    }

    // merge chunk maxima, ascending order + strict > keeps first-argmin ties
    float best = m[0]; int bc = 0;
    #pragma unroll
    for (int c = 1; c < NCH; c++) if (m[c] > best) { best = m[c]; bc = c; }
    // exact index recovery in winning chunk
    const float4* sv = s_v + bc * CL;
    int idx = -1;
    for (int k = 0; k < CL; k++) {
        float4 q = sv[k];
        float t = fmaf(q.x, ox, fmaf(q.y, oy, fmaf(q.z, oz, -q.w)));
        if (idx < 0 && t == best) idx = k;
    }
    const int bi = bc * CL + idx;

    float o2 = ox * ox + oy * oy + oz * oz;
    float d2 = fmaf(-2.f, best, o2);
    out[OFF_CMAP + b * NOBJ + pt] = 2.f / (1.f + __expf(100.f * d2));

    float4 q = s_v[bi];
    const float* gn = g_normals + (b * NV + bi) * 3;
    float dp = (q.x - ox) * gn[0] + (q.y - oy) * gn[1] + (q.z - oz) * gn[2];
    float pen = (dp > 0.f) ? d2 : 0.f;

    #pragma unroll
    for (int off = 16; off > 0; off >>= 1) pen += __shfl_down_sync(0xffffffffu, pen, off);
    if ((tid & 31) == 0) s_red[tid >> 5] = pen;
    __syncthreads();
    if (tid == 0) {
        float s = 0.f;
        #pragma unroll
        for (int w = 0; w < 8; w++) s += s_red[w];
        atomicAdd(&out[OFF_PEN], s * (1.f / NB));
    }
}

// ---------------------------------------------------------------------------
extern "C" void kernel_launch(void* const* d_in, const int* in_sizes, int n_in,
                              void* d_out, int out_size)
{
    const float* hand_pose  = (const float*)d_in[0];
    const float* obj_points = (const float*)d_in[1];
    const float* hand_beta  = (const float*)d_in[2];
    const float* v_template = (const float*)d_in[3];
    const float* shapedirs  = (const float*)d_in[4];
    const float* posedirs   = (const float*)d_in[5];
    const float* J_reg      = (const float*)d_in[6];
    const float* lbs_w      = (const float*)d_in[7];
    const float* pca        = (const float*)d_in[8];
    const float* aw         = (const float*)d_in[9];
    const int*   faces      = (const int*)d_in[10];
    const int*   afi        = (const int*)d_in[11];
    float* out = (float*)d_out;

    prep_a_kernel<<<48, 128>>>(J_reg, shapedirs, v_template, out);
    prep_b_kernel<<<1, 256>>>(hand_pose, hand_beta, pca);
    vert_kernel<<<NB * 8, 256>>>(v_template, shapedirs, posedirs, lbs_w,
                                 hand_pose, hand_beta, out);
    norm_kernel<<<NB, 256>>>(faces, aw, afi, out);
    nn_kernel<<<NB * 64, 256>>>(obj_points, out);
}

// round 8
// speedup vs baseline: 2.1887x; 1.6386x over previous
#include <cuda_runtime.h>
#include <math.h>

#define NV 778
#define VP 784            // 8*98 verts, 392 pairs
#define NP 392            // vertex pairs
#define NJ 16
#define NCOMP 24
#define NBETA 10
#define FC 1554
#define NA 32
#define NB 8
#define NOBJ 16384

#define NCH 8
#define CPL 49            // pairs per chunk (8*49 = 392)

#define OFF_CMAP 0
#define OFF_PEN  (NB*NOBJ)
#define OFF_VERTS (OFF_PEN + 1)
#define OFF_CC   (OFF_VERTS + NB*NV*3)

// pair-interleaved vertex data:
//  g_vpA[p] = { X=(x0,x1), Y=(y0,y1) }   g_vpB[p] = { Z=(z0,z1), Wn=(wn0,wn1) }
//  wn = -0.5*|v|^2  (sentinel: x=y=z=0, wn=-1e30)
__device__ ulonglong2 g_vpA[NB * NP];
__device__ ulonglong2 g_vpB[NB * NP];
__device__ float  g_normals[NB * NV * 3];  // UNNORMALIZED (sign-only use)
__device__ float  g_A[NB * NJ * 12];       // skinning transforms
__device__ float  g_pf[NB * 135];          // pose features

__constant__ int c_parents[NJ] = {-1,0,1,2,0,4,5,0,7,8,0,10,11,0,13,14};

__device__ __forceinline__ unsigned long long pack2(float v) {
    unsigned long long r; unsigned u = __float_as_uint(v);
    asm("mov.b64 %0, {%1, %1};" : "=l"(r) : "r"(u));
    return r;
}
__device__ __forceinline__ void unpack2(unsigned long long v, float& lo, float& hi) {
    unsigned a, b;
    asm("mov.b64 {%0, %1}, %2;" : "=r"(a), "=r"(b) : "l"(v));
    lo = __uint_as_float(a); hi = __uint_as_float(b);
}
#define FMA2(d,a,b,c) asm("fma.rn.f32x2 %0, %1, %2, %3;" : "=l"(d) : "l"(a), "l"(b), "l"(c))

// ---------------------------------------------------------------------------
// prep: per-batch pose pipeline (grid NB, 256 thr)
//   v_shaped -> J -> rodrigues -> pose features -> kinematic chain -> g_A
//   also zeroes g_normals slice and penetration slot
// ---------------------------------------------------------------------------
__global__ void __launch_bounds__(256) prep_kernel(
    const float* __restrict__ hand_pose, const float* __restrict__ hand_beta,
    const float* __restrict__ pca, const float* __restrict__ v_template,
    const float* __restrict__ shapedirs, const float* __restrict__ J_reg,
    float* __restrict__ out)
{
    __shared__ float s_pose[32];
    __shared__ float s_beta[NBETA];
    __shared__ float s_full[48];
    __shared__ float s_R[NJ * 9];
    __shared__ float s_J[48];
    __shared__ float s_T[NJ * 12];
    __shared__ float s_vsh[NV * 3];

    const int b = blockIdx.x;
    const int tid = threadIdx.x;
    const int wid = tid >> 5, lane = tid & 31;

    if (tid < 30) s_pose[tid] = hand_pose[b * 30 + tid];
    if (tid >= 32 && tid < 32 + NBETA) s_beta[tid - 32] = hand_beta[b * NBETA + (tid - 32)];
    for (int i = tid; i < NV * 3; i += 256) g_normals[b * NV * 3 + i] = 0.f;
    if (b == 0 && tid == 0) out[OFF_PEN] = 0.f;
    __syncthreads();

    // full pose + v_shaped
    if (tid < 3) s_full[tid] = s_pose[3 + tid];
    if (tid >= 64 && tid < 64 + 45) {
        int p = tid - 64;
        float acc = 0.f;
        #pragma unroll
        for (int k = 0; k < NCOMP; k++) acc = fmaf(s_pose[6 + k], pca[k * 45 + p], acc);
        s_full[3 + p] = acc;
    }
    for (int i = tid; i < NV * 3; i += 256) {
        const float2* sd = (const float2*)shapedirs + i * 5;
        float2 d0 = sd[0], d1 = sd[1], d2 = sd[2], d3 = sd[3], d4 = sd[4];
        float acc = v_template[i];
        acc = fmaf(d0.x, s_beta[0], acc); acc = fmaf(d0.y, s_beta[1], acc);
        acc = fmaf(d1.x, s_beta[2], acc); acc = fmaf(d1.y, s_beta[3], acc);
        acc = fmaf(d2.x, s_beta[4], acc); acc = fmaf(d2.y, s_beta[5], acc);
        acc = fmaf(d3.x, s_beta[6], acc); acc = fmaf(d3.y, s_beta[7], acc);
        acc = fmaf(d4.x, s_beta[8], acc); acc = fmaf(d4.y, s_beta[9], acc);
        s_vsh[i] = acc;
    }
    __syncthreads();

    // rodrigues
    if (tid < NJ) {
        float rx = s_full[tid * 3 + 0], ry = s_full[tid * 3 + 1], rz = s_full[tid * 3 + 2];
        float th = sqrtf(rx * rx + ry * ry + rz * rz + 1e-16f);
        float inv = 1.f / th;
        float kx = rx * inv, ky = ry * inv, kz = rz * inv;
        float c, s;
        sincosf(th, &s, &c);
        float ic = 1.f - c;
        float* R = &s_R[tid * 9];
        R[0] = c + ic * kx * kx;       R[1] = -s * kz + ic * kx * ky; R[2] =  s * ky + ic * kx * kz;
        R[3] =  s * kz + ic * ky * kx; R[4] = c + ic * ky * ky;       R[5] = -s * kx + ic * ky * kz;
        R[6] = -s * ky + ic * kz * kx; R[7] =  s * kx + ic * kz * ky; R[8] = c + ic * kz * kz;
    }
    // J = J_reg @ v_shaped (warp-coop, 8 warps x 6 outputs)
    #pragma unroll
    for (int q = 0; q < 6; q++) {
        int o = wid + 8 * q;
        int j = o / 3, d = o % 3;
        const float* jr = J_reg + j * NV;
        float acc = 0.f;
        #pragma unroll
        for (int k = 0; k < 25; k++) {
            int v = lane + 32 * k;
            if (v < NV) acc = fmaf(jr[v], s_vsh[v * 3 + d], acc);
        }
        #pragma unroll
        for (int off = 16; off > 0; off >>= 1) acc += __shfl_xor_sync(0xffffffffu, acc, off);
        if (lane == 0) s_J[o] = acc;
    }
    __syncthreads();

    // pose features
    if (tid >= 64 && tid < 64 + 135) {
        int p = tid - 64;
        int e = p % 9;
        float diag = ((e == 0) | (e == 4) | (e == 8)) ? 1.f : 0.f;
        g_pf[b * 135 + p] = s_R[(1 + p / 9) * 9 + e] - diag;
    }

    // kinematic chain (warp 0, level-parallel)
    if (wid == 0 && lane < 16) {
        const int j = lane;
        const int p = c_parents[j];
        float L[12];
        #pragma unroll
        for (int e = 0; e < 9; e++) L[(e / 3) * 4 + (e % 3)] = s_R[j * 9 + e];
        float jx = s_J[j * 3 + 0], jy = s_J[j * 3 + 1], jz = s_J[j * 3 + 2];
        if (j == 0) { L[3] = jx; L[7] = jy; L[11] = jz; }
        else {
            L[3]  = jx - s_J[p * 3 + 0];
            L[7]  = jy - s_J[p * 3 + 1];
            L[11] = jz - s_J[p * 3 + 2];
        }
        const int depth = (j == 0) ? 0 : ((j - 1) % 3) + 1;
        if (depth == 0) {
            #pragma unroll
            for (int k = 0; k < 12; k++) s_T[k] = L[k];
        }
        __syncwarp(0xffffu);
        #pragma unroll
        for (int l = 1; l <= 3; l++) {
            if (depth == l) {
                float Tp[12];
                #pragma unroll
                for (int k = 0; k < 12; k++) Tp[k] = s_T[p * 12 + k];
                #pragma unroll
                for (int r = 0; r < 3; r++) {
                    #pragma unroll
                    for (int c2 = 0; c2 < 4; c2++) {
                        float acc = (c2 == 3) ? Tp[r * 4 + 3] : 0.f;
                        #pragma unroll
                        for (int k = 0; k < 3; k++) acc = fmaf(Tp[r * 4 + k], L[k * 4 + c2], acc);
                        s_T[j * 12 + r * 4 + c2] = acc;
                    }
                }
            }
            __syncwarp(0xffffu);
        }
        #pragma unroll
        for (int r = 0; r < 3; r++) {
            float r0 = s_T[j * 12 + r * 4 + 0], r1 = s_T[j * 12 + r * 4 + 1], r2 = s_T[j * 12 + r * 4 + 2];
            g_A[(b * NJ + j) * 12 + r * 4 + 0] = r0;
            g_A[(b * NJ + j) * 12 + r * 4 + 1] = r1;
            g_A[(b * NJ + j) * 12 + r * 4 + 2] = r2;
            g_A[(b * NJ + j) * 12 + r * 4 + 3] = s_T[j * 12 + r * 4 + 3] - (r0 * jx + r1 * jy + r2 * jz);
        }
    }
}

// ---------------------------------------------------------------------------
// vert: v_shaped + posedirs einsum + LBS. grid NB*16 (49 verts/block), 256 thr
// ---------------------------------------------------------------------------
__global__ void __launch_bounds__(256) vert_kernel(
    const float* __restrict__ v_template, const float* __restrict__ shapedirs,
    const float* __restrict__ posedirs, const float* __restrict__ lbs_w,
    const float* __restrict__ hand_pose, const float* __restrict__ hand_beta,
    float* __restrict__ out)
{
    __shared__ float s_A[NJ * 12];
    __shared__ float s_vp[49 * 3];
    __shared__ float s_beta[NBETA];

    const int b = blockIdx.x >> 4;
    const int chunk = blockIdx.x & 15;
    const int vbase = chunk * 49;
    const int tid = threadIdx.x;
    const int wid = tid >> 5, lane = tid & 31;

    if (tid < NJ * 12) s_A[tid] = g_A[b * NJ * 12 + tid];
    if (tid >= 192 && tid < 192 + NBETA) s_beta[tid - 192] = hand_beta[b * NBETA + (tid - 192)];
    __syncthreads();

    float pfr[5];
    #pragma unroll
    for (int jj = 0; jj < 5; jj++) {
        int p = lane + 32 * jj;
        pfr[jj] = (p < 135) ? g_pf[b * 135 + p] : 0.f;
    }

    for (int r = wid; r < 49 * 3; r += 8) {
        int row = vbase * 3 + r;
        if (row < NV * 3) {
            const float* pd = posedirs + row * 135;
            float a = pfr[0] * pd[lane];
            a = fmaf(pfr[1], pd[lane + 32], a);
            a = fmaf(pfr[2], pd[lane + 64], a);
            a = fmaf(pfr[3], pd[lane + 96], a);
            if (lane < 7) a = fmaf(pfr[4], pd[lane + 128], a);
            #pragma unroll
            for (int off = 16; off > 0; off >>= 1)
                a += __shfl_xor_sync(0xffffffffu, a, off);
            if (lane == 0) {
                const float* sd = shapedirs + row * NBETA;
                float base = v_template[row];
                #pragma unroll
                for (int k = 0; k < NBETA; k++) base = fmaf(sd[k], s_beta[k], base);
                s_vp[r] = base + a;
            }
        }
    }
    __syncthreads();

    if (tid < 49) {
        int v = vbase + tid;
        if (v < NV) {
            const float4* w4 = (const float4*)(lbs_w + v * NJ);
            float4 a0 = w4[0], a1 = w4[1], a2 = w4[2], a3 = w4[3];
            float wj[16] = {a0.x,a0.y,a0.z,a0.w, a1.x,a1.y,a1.z,a1.w,
                            a2.x,a2.y,a2.z,a2.w, a3.x,a3.y,a3.z,a3.w};
            float M[12];
            #pragma unroll
            for (int k = 0; k < 12; k++) M[k] = 0.f;
            #pragma unroll
            for (int j = 0; j < NJ; j++) {
                #pragma unroll
                for (int k = 0; k < 12; k++) M[k] = fmaf(wj[j], s_A[j * 12 + k], M[k]);
            }
            float x = s_vp[tid * 3 + 0], y = s_vp[tid * 3 + 1], z = s_vp[tid * 3 + 2];
            float px = fmaf(M[0], x, fmaf(M[1],  y, fmaf(M[2],  z, M[3])))  + hand_pose[b * 30 + 0];
            float py = fmaf(M[4], x, fmaf(M[5],  y, fmaf(M[6],  z, M[7])))  + hand_pose[b * 30 + 1];
            float pz = fmaf(M[8], x, fmaf(M[9],  y, fmaf(M[10], z, M[11]))) + hand_pose[b * 30 + 2];
            out[OFF_VERTS + (b * NV + v) * 3 + 0] = px;
            out[OFF_VERTS + (b * NV + v) * 3 + 1] = py;
            out[OFF_VERTS + (b * NV + v) * 3 + 2] = pz;
            int p = v >> 1, i = v & 1;
            float* A = (float*)&g_vpA[b * NP + p];
            float* B = (float*)&g_vpB[b * NP + p];
            A[i] = px; A[2 + i] = py;
            B[i] = pz; B[2 + i] = -0.5f * (px * px + py * py + pz * pz);
        } else if (v < VP) {
            int p = v >> 1, i = v & 1;
            float* A = (float*)&g_vpA[b * NP + p];
            float* B = (float*)&g_vpB[b * NP + p];
            A[i] = 0.f; A[2 + i] = 0.f;
            B[i] = 0.f; B[2 + i] = -1e30f;   // sentinel: never wins
        }
    }
}

// ---------------------------------------------------------------------------
// scatter: face-normal accumulation (global atomics) + contact candidates
// grid 50: blocks 0..48 faces, block 49 contacts
// ---------------------------------------------------------------------------
__global__ void __launch_bounds__(256) scatter_kernel(
    const int* __restrict__ faces, const float* __restrict__ aw,
    const int* __restrict__ afi, float* __restrict__ out)
{
    const int tid = threadIdx.x;
    if (blockIdx.x < 49) {
        int i = blockIdx.x * 256 + tid;
        if (i >= NB * FC) return;
        int b = i / FC, f = i % FC;
        const float* vb = out + OFF_VERTS + b * NV * 3;
        int i0 = faces[f * 3 + 0], i1 = faces[f * 3 + 1], i2 = faces[f * 3 + 2];
        float p0x = vb[i0*3+0], p0y = vb[i0*3+1], p0z = vb[i0*3+2];
        float e1x = vb[i1*3+0]-p0x, e1y = vb[i1*3+1]-p0y, e1z = vb[i1*3+2]-p0z;
        float e2x = vb[i2*3+0]-p0x, e2y = vb[i2*3+1]-p0y, e2z = vb[i2*3+2]-p0z;
        float nx = e1y * e2z - e1z * e2y;
        float ny = e1z * e2x - e1x * e2z;
        float nz = e1x * e2y - e1y * e2x;
        float* gn = g_normals + b * NV * 3;
        atomicAdd(&gn[i0*3+0], nx); atomicAdd(&gn[i0*3+1], ny); atomicAdd(&gn[i0*3+2], nz);
        atomicAdd(&gn[i1*3+0], nx); atomicAdd(&gn[i1*3+1], ny); atomicAdd(&gn[i1*3+2], nz);
        atomicAdd(&gn[i2*3+0], nx); atomicAdd(&gn[i2*3+1], ny); atomicAdd(&gn[i2*3+2], nz);
    } else {
        for (int t = tid; t < NB * NA * 3; t += 256) {
            int b = t / (NA * 3);
            int r = t % (NA * 3);
            int a = r / 3, d = r % 3;
            const float* vb = out + OFF_VERTS + b * NV * 3;
            float acc = 0.f;
            #pragma unroll
            for (int k = 0; k < 3; k++)
                acc = fmaf(aw[a * 3 + k], vb[afi[a * 3 + k] * 3 + d], acc);
            out[OFF_CC + t] = acc;
        }
    }
}

// ---------------------------------------------------------------------------
// nn: fused NN + cmap + penetration. grid NB*64, 128 thr, 2 pts/thread
// packed f32x2: t = fma(X,OX, fma(Y,OY, fma(Z,OZ, Wn)))  (Wn = -0.5|v|^2)
// argmin d2 == argmax t ; d2 = |o|^2 - 2t
// ---------------------------------------------------------------------------
__global__ void __launch_bounds__(128) nn_kernel(const float* __restrict__ obj,
                                                 float* __restrict__ out)
{
    __shared__ ulonglong2 s_a[NP];
    __shared__ ulonglong2 s_b[NP];
    __shared__ float s_red[4];

    const int b = blockIdx.x >> 6;
    const int tile = blockIdx.x & 63;
    const int tid = threadIdx.x;

    for (int p = tid; p < NP; p += 128) {
        s_a[p] = g_vpA[b * NP + p];
        s_b[p] = g_vpB[b * NP + p];
    }
    __syncthreads();

    const int pt0 = tile * 256 + tid;
    const int pt1 = pt0 + 128;
    const float* o0 = obj + (b * NOBJ + pt0) * 3;
    const float* o1 = obj + (b * NOBJ + pt1) * 3;
    const float ax = o0[0], ay = o0[1], az = o0[2];
    const float bx = o1[0], by = o1[1], bz = o1[2];

    const unsigned long long AX = pack2(ax), AY = pack2(ay), AZ = pack2(az);
    const unsigned long long BX = pack2(bx), BY = pack2(by), BZ = pack2(bz);

    float meA[NCH], moA[NCH], meB[NCH], moB[NCH];

    #pragma unroll
    for (int c = 0; c < NCH; c++) {
        const ulonglong2* pa = s_a + c * CPL;
        const ulonglong2* pb = s_b + c * CPL;
        float e0 = -3.4e38f, h0 = -3.4e38f, e1 = -3.4e38f, h1 = -3.4e38f;
        #pragma unroll 7
        for (int k = 0; k < CPL; k++) {
            ulonglong2 A = pa[k], B = pb[k];
            unsigned long long t;
            float lo, hi;
            FMA2(t, B.x, AZ, B.y);
            FMA2(t, A.y, AY, t);
            FMA2(t, A.x, AX, t);
            unpack2(t, lo, hi);
            e0 = fmaxf(e0, lo); h0 = fmaxf(h0, hi);
            FMA2(t, B.x, BZ, B.y);
            FMA2(t, A.y, BY, t);
            FMA2(t, A.x, BX, t);
            unpack2(t, lo, hi);
            e1 = fmaxf(e1, lo); h1 = fmaxf(h1, hi);
        }
        meA[c] = e0; moA[c] = h0; meB[c] = e1; moB[c] = h1;
    }

    float pen = 0.f;
    #pragma unroll
    for (int ptsel = 0; ptsel < 2; ptsel++) {
        const float ox = ptsel ? bx : ax;
        const float oy = ptsel ? by : ay;
        const float oz = ptsel ? bz : az;
        const float* me = ptsel ? meB : meA;
        const float* mo = ptsel ? moB : moA;
        const int pt = ptsel ? pt1 : pt0;

        float best = fmaxf(me[0], mo[0]); int bc = 0;
        #pragma unroll
        for (int c = 1; c < NCH; c++) {
            float cm = fmaxf(me[c], mo[c]);
            if (cm > best) { best = cm; bc = c; }
        }
        // exact in-order index recovery in winning chunk
        const float* fa = (const float*)(s_a + bc * CPL);
        const float* fb = (const float*)(s_b + bc * CPL);
        int idx = -1;
        for (int k = 0; k < CPL; k++) {
            float t0 = fmaf(fa[4*k+0], ox, fmaf(fa[4*k+2], oy, fmaf(fb[4*k+0], oz, fb[4*k+2])));
            float t1 = fmaf(fa[4*k+1], ox, fmaf(fa[4*k+3], oy, fmaf(fb[4*k+1], oz, fb[4*k+3])));
            if (idx < 0 && t0 == best) idx = 2 * k;
            if (idx < 0 && t1 == best) idx = 2 * k + 1;
        }
        const int bi = bc * (2 * CPL) + idx;

        float o2 = ox * ox + oy * oy + oz * oz;
        float d2 = fmaf(-2.f, best, o2);
        out[OFF_CMAP + b * NOBJ + pt] = 2.f / (1.f + __expf(100.f * d2));

        int pp = bi >> 1, ii = bi & 1;
        const float* Af = (const float*)&s_a[pp];
        const float* Bf = (const float*)&s_b[pp];
        float vx = Af[ii], vy = Af[2 + ii], vz = Bf[ii];
        const float* gn = g_normals + (b * NV + bi) * 3;
        float dp = (vx - ox) * gn[0] + (vy - oy) * gn[1] + (vz - oz) * gn[2];
        pen += (dp > 0.f) ? d2 : 0.f;
    }

    #pragma unroll
    for (int off = 16; off > 0; off >>= 1) pen += __shfl_down_sync(0xffffffffu, pen, off);
    if ((tid & 31) == 0) s_red[tid >> 5] = pen;
    __syncthreads();
    if (tid == 0) {
        float s = s_red[0] + s_red[1] + s_red[2] + s_red[3];
        atomicAdd(&out[OFF_PEN], s * (1.f / NB));
    }
}

// ---------------------------------------------------------------------------
extern "C" void kernel_launch(void* const* d_in, const int* in_sizes, int n_in,
                              void* d_out, int out_size)
{
    const float* hand_pose  = (const float*)d_in[0];
    const float* obj_points = (const float*)d_in[1];
    const float* hand_beta  = (const float*)d_in[2];
    const float* v_template = (const float*)d_in[3];
    const float* shapedirs  = (const float*)d_in[4];
    const float* posedirs   = (const float*)d_in[5];
    const float* J_reg      = (const float*)d_in[6];
    const float* lbs_w      = (const float*)d_in[7];
    const float* pca        = (const float*)d_in[8];
    const float* aw         = (const float*)d_in[9];
    const int*   faces      = (const int*)d_in[10];
    const int*   afi        = (const int*)d_in[11];
    float* out = (float*)d_out;

    prep_kernel<<<NB, 256>>>(hand_pose, hand_beta, pca, v_template,
                             shapedirs, J_reg, out);
    vert_kernel<<<NB * 16, 256>>>(v_template, shapedirs, posedirs, lbs_w,
                                  hand_pose, hand_beta, out);
    scatter_kernel<<<50, 256>>>(faces, aw, afi, out);
    nn_kernel<<<NB * 64, 128>>>(obj_points, out);
}